// round 1
// baseline (speedup 1.0000x reference)
#include <cuda_runtime.h>
#include <math.h>
#include <stdint.h>

// ---------------------------------------------------------------------------
// Problem constants (fixed by setup_inputs)
// ---------------------------------------------------------------------------
#define NAC 20000
#define NBC 20000
#define NNC 40000
#define EC  150000

// ---------------------------------------------------------------------------
// Scratch (static __device__ globals; no runtime allocation)
// ---------------------------------------------------------------------------
__device__ float    g_h[NNC * 128];          // node features, concat [a;b]
__device__ float    g_kqv[2 * NAC * 384];    // per-type kqv
__device__ float    g_kt[3 * NAC * 128];     // per-edge-type transformed k
__device__ float    g_vt[3 * NAC * 128];     // per-edge-type transformed v
__device__ float    g_alpha[3 * EC * 4];     // per-edge, per-head logits/weights
__device__ unsigned g_segmax[NNC * 4];       // encoded float max
__device__ float    g_segsum[NNC * 4];
__device__ float    g_agg[NNC * 128];
__device__ float    g_gout[NNC * 128];
__device__ float    g_x1[NNC];
__device__ unsigned g_gmax[NNC];
__device__ float    g_gsum[NNC];
__device__ float    g_gnum[NNC];
__device__ float    g_score[NNC];
__device__ float    g_stmp[NNC];

// ---------------------------------------------------------------------------
// Helpers
// ---------------------------------------------------------------------------
__device__ __forceinline__ float gelu_f(float x) {
    return 0.5f * x * (1.0f + erff(x * 0.7071067811865475f));
}
// Monotone float -> uint encoding (total order), for atomicMax on floats.
__device__ __forceinline__ unsigned fenc(float f) {
    unsigned u = __float_as_uint(f);
    return (u >> 31) ? ~u : (u | 0x80000000u);
}
__device__ __forceinline__ float fdec(unsigned e) {
    unsigned u = (e >> 31) ? (e & 0x7FFFFFFFu) : ~e;
    return __uint_as_float(u);
}
#define ENC_NEG_INF 0x007FFFFFu   // fenc(-inf)

// ---------------------------------------------------------------------------
// Copy inputs into concat feature buffer
// ---------------------------------------------------------------------------
__global__ void k_copy_in(const float* __restrict__ xa, const float* __restrict__ xb,
                          float* __restrict__ h, int na128, int nb128) {
    int i = blockIdx.x * blockDim.x + threadIdx.x;
    if (i < na128) h[i] = xa[i];
    if (i < nb128) h[na128 + i] = xb[i];
}

// ---------------------------------------------------------------------------
// Generic SGEMM: C[M,N] = A[M,K](lda) @ B[K,N](ldb) + bias (optional)
// 64x64 tile, BK=16, 256 threads, 4x4 per-thread register tile.
// Requires K % 16 == 0, lda % 4 == 0, 16B-aligned A/B. (All call sites satisfy.)
// ---------------------------------------------------------------------------
__global__ void k_sgemm(const float* __restrict__ A, int lda,
                        const float* __restrict__ B, int ldb,
                        const float* __restrict__ bias,
                        float* __restrict__ C, int ldc,
                        int M, int N, int K) {
    __shared__ __align__(16) float As[16 * 64];
    __shared__ __align__(16) float Bs[16 * 64];
    int tid = threadIdx.x;
    int tx = tid & 15, ty = tid >> 4;
    int row0 = blockIdx.y * 64, col0 = blockIdx.x * 64;
    float acc[4][4] = {};

    int amm = tid >> 2;          // 0..63
    int akk = (tid & 3) * 4;     // 0,4,8,12
    int bkk = tid >> 4;          // 0..15
    int bnn = (tid & 15) * 4;    // 0..60

    for (int k0 = 0; k0 < K; k0 += 16) {
        float4 a4 = make_float4(0.f, 0.f, 0.f, 0.f);
        int arow = row0 + amm;
        if (arow < M) a4 = *(const float4*)(A + (size_t)arow * lda + k0 + akk);
        As[(akk + 0) * 64 + amm] = a4.x;
        As[(akk + 1) * 64 + amm] = a4.y;
        As[(akk + 2) * 64 + amm] = a4.z;
        As[(akk + 3) * 64 + amm] = a4.w;

        float4 b4 = make_float4(0.f, 0.f, 0.f, 0.f);
        int bcol = col0 + bnn;
        if (bcol < N) b4 = *(const float4*)(B + (size_t)(k0 + bkk) * ldb + bcol);
        *(float4*)&Bs[bkk * 64 + bnn] = b4;
        __syncthreads();

#pragma unroll
        for (int kk = 0; kk < 16; kk++) {
            float4 a = *(const float4*)&As[kk * 64 + ty * 4];
            float4 b = *(const float4*)&Bs[kk * 64 + tx * 4];
            acc[0][0] += a.x * b.x; acc[0][1] += a.x * b.y; acc[0][2] += a.x * b.z; acc[0][3] += a.x * b.w;
            acc[1][0] += a.y * b.x; acc[1][1] += a.y * b.y; acc[1][2] += a.y * b.z; acc[1][3] += a.y * b.w;
            acc[2][0] += a.z * b.x; acc[2][1] += a.z * b.y; acc[2][2] += a.z * b.z; acc[2][3] += a.z * b.w;
            acc[3][0] += a.w * b.x; acc[3][1] += a.w * b.y; acc[3][2] += a.w * b.z; acc[3][3] += a.w * b.w;
        }
        __syncthreads();
    }

#pragma unroll
    for (int i = 0; i < 4; i++) {
        int r = row0 + ty * 4 + i;
        if (r >= M) continue;
#pragma unroll
        for (int j = 0; j < 4; j++) {
            int c = col0 + tx * 4 + j;
            if (c < N) {
                float v = acc[i][j];
                if (bias) v += bias[c];
                C[(size_t)r * ldc + c] = v;
            }
        }
    }
}

// ---------------------------------------------------------------------------
// Per-head 32x32 relation transform: kt[n,h,e] = sum_d k[n,h,d]*arel[h,d,e]
// (and vt with mrel). k at kqv cols [0,128), v at cols [256,384).
// Block: 128 threads = (h, e); grid-stride over nodes.
// ---------------------------------------------------------------------------
__global__ void k_rel_transform(const float* __restrict__ kqv,
                                const float* __restrict__ arel,
                                const float* __restrict__ mrel,
                                float* __restrict__ kt, float* __restrict__ vt,
                                int Nn) {
    __shared__ float sA[4096], sM[4096];
    __shared__ float sK[128], sV[128];
    for (int i = threadIdx.x; i < 4096; i += 128) { sA[i] = arel[i]; sM[i] = mrel[i]; }
    __syncthreads();
    int h = threadIdx.x >> 5, e = threadIdx.x & 31;
    const float* a = &sA[h * 1024 + e];
    const float* m = &sM[h * 1024 + e];
    const float* kk = &sK[h * 32];
    const float* vv = &sV[h * 32];
    for (int n = blockIdx.x; n < Nn; n += gridDim.x) {
        sK[threadIdx.x] = kqv[(size_t)n * 384 + threadIdx.x];
        sV[threadIdx.x] = kqv[(size_t)n * 384 + 256 + threadIdx.x];
        __syncthreads();
        float ak = 0.f, av = 0.f;
#pragma unroll
        for (int d = 0; d < 32; d++) {
            ak += kk[d] * a[d * 32];
            av += vv[d] * m[d * 32];
        }
        kt[(size_t)n * 128 + threadIdx.x] = ak;
        vt[(size_t)n * 128 + threadIdx.x] = av;
        __syncthreads();
    }
}

// ---------------------------------------------------------------------------
// Segment softmax buffers init
// ---------------------------------------------------------------------------
__global__ void k_init_seg(unsigned* __restrict__ segmax, float* __restrict__ segsum,
                           float* __restrict__ agg, int N) {
    int i = blockIdx.x * blockDim.x + threadIdx.x;
    if (i < N * 128) agg[i] = 0.f;
    if (i < N * 4) { segmax[i] = ENC_NEG_INF; segsum[i] = 0.f; }
}

// ---------------------------------------------------------------------------
// Edge pass A: alpha[e,h] = (q[dst,h,:] . kt[src,h,:]) * prel[h] / sqrt(32)
//              + encoded atomicMax into segmax.  One warp per edge.
// ---------------------------------------------------------------------------
__global__ void k_edge_alpha(const int* __restrict__ ei,
                             const float* __restrict__ kqv_dst,
                             const float* __restrict__ kt,
                             const float* __restrict__ prel,
                             float* __restrict__ alpha,
                             unsigned* __restrict__ segmax,
                             int E, int dstOff) {
    int gw = (blockIdx.x * blockDim.x + threadIdx.x) >> 5;
    int lane = threadIdx.x & 31;
    int nw = (gridDim.x * blockDim.x) >> 5;
    for (int e = gw; e < E; e += nw) {
        int src = ei[e];
        int dst = ei[E + e];
        const float* q = kqv_dst + (size_t)dst * 384 + 128;
        const float* k = kt + (size_t)src * 128;
#pragma unroll
        for (int h = 0; h < 4; h++) {
            float v = q[h * 32 + lane] * k[h * 32 + lane];
            v += __shfl_down_sync(0xffffffffu, v, 16);
            v += __shfl_down_sync(0xffffffffu, v, 8);
            v += __shfl_down_sync(0xffffffffu, v, 4);
            v += __shfl_down_sync(0xffffffffu, v, 2);
            v += __shfl_down_sync(0xffffffffu, v, 1);
            if (lane == 0) {
                float a = v * prel[h] * 0.17677669529663687f; // 1/sqrt(32)
                alpha[(size_t)e * 4 + h] = a;
                atomicMax(&segmax[(size_t)(dst + dstOff) * 4 + h], fenc(a));
            }
        }
    }
}

// ---------------------------------------------------------------------------
// Edge pass B: alpha <- exp(alpha - max); segsum += alpha
// ---------------------------------------------------------------------------
__global__ void k_edge_expsum(float* __restrict__ alpha, const int* __restrict__ ei,
                              const unsigned* __restrict__ segmax,
                              float* __restrict__ segsum, int E, int dstOff) {
    int i = blockIdx.x * blockDim.x + threadIdx.x;
    if (i >= E * 4) return;
    int e = i >> 2, h = i & 3;
    int dst = ei[E + e] + dstOff;
    float m = fdec(segmax[(size_t)dst * 4 + h]);
    float w = expf(alpha[i] - m);
    alpha[i] = w;
    atomicAdd(&segsum[(size_t)dst * 4 + h], w);
}

// ---------------------------------------------------------------------------
// Edge pass C: agg[dst,h,:] += (alpha/(sum+eps)) * vt[src,h,:]. Warp per edge.
// ---------------------------------------------------------------------------
__global__ void k_edge_scatter(const float* __restrict__ alpha, const int* __restrict__ ei,
                               const float* __restrict__ segsum,
                               const float* __restrict__ vt,
                               float* __restrict__ agg, int E, int dstOff) {
    int gw = (blockIdx.x * blockDim.x + threadIdx.x) >> 5;
    int lane = threadIdx.x & 31;
    int nw = (gridDim.x * blockDim.x) >> 5;
    for (int e = gw; e < E; e += nw) {
        int src = ei[e];
        int dst = ei[E + e] + dstOff;
#pragma unroll
        for (int h = 0; h < 4; h++) {
            float w = alpha[(size_t)e * 4 + h] / (segsum[(size_t)dst * 4 + h] + 1e-16f);
            atomicAdd(&agg[(size_t)dst * 128 + h * 32 + lane],
                      w * vt[(size_t)src * 128 + h * 32 + lane]);
        }
    }
}

// ---------------------------------------------------------------------------
// Elementwise GELU (in place)
// ---------------------------------------------------------------------------
__global__ void k_gelu(float* __restrict__ x, int n) {
    int i = blockIdx.x * blockDim.x + threadIdx.x;
    if (i < n) x[i] = gelu_f(x[i]);
}

// ---------------------------------------------------------------------------
// Finish epilogue: h = gelu( [LN]( s*g + (1-s)*h ) ). One block (128 thr)/row.
// ---------------------------------------------------------------------------
__global__ void k_epilogue(const float* __restrict__ g, float* __restrict__ h,
                           const float* __restrict__ skipv,
                           const float* __restrict__ lng, const float* __restrict__ lnb,
                           int doLN) {
    int n = blockIdx.x, t = threadIdx.x;
    float s = 1.0f / (1.0f + expf(-skipv[0]));
    size_t idx = (size_t)n * 128 + t;
    float v = s * g[idx] + (1.0f - s) * h[idx];
    if (doLN) {
        float sv = v, sq = v * v;
#pragma unroll
        for (int o = 16; o > 0; o >>= 1) {
            sv += __shfl_down_sync(0xffffffffu, sv, o);
            sq += __shfl_down_sync(0xffffffffu, sq, o);
        }
        __shared__ float s1[4], s2[4];
        int w = t >> 5;
        if ((t & 31) == 0) { s1[w] = sv; s2[w] = sq; }
        __syncthreads();
        float mu = (s1[0] + s1[1] + s1[2] + s1[3]) * 0.0078125f;
        float eq = (s2[0] + s2[1] + s2[2] + s2[3]) * 0.0078125f;
        float var = eq - mu * mu;
        v = (v - mu) * rsqrtf(var + 1e-5f) * lng[t] + lnb[t];
    }
    h[idx] = gelu_f(v);
}

// ---------------------------------------------------------------------------
// GAT scorer
// ---------------------------------------------------------------------------
__global__ void k_x1(const float* __restrict__ h, const float* __restrict__ Wg,
                     float* __restrict__ x1, int N) {
    int gw = (blockIdx.x * blockDim.x + threadIdx.x) >> 5;
    int lane = threadIdx.x & 31;
    if (gw >= N) return;
    const float* row = h + (size_t)gw * 128;
    float v = row[lane] * Wg[lane] + row[32 + lane] * Wg[32 + lane]
            + row[64 + lane] * Wg[64 + lane] + row[96 + lane] * Wg[96 + lane];
    v += __shfl_down_sync(0xffffffffu, v, 16);
    v += __shfl_down_sync(0xffffffffu, v, 8);
    v += __shfl_down_sync(0xffffffffu, v, 4);
    v += __shfl_down_sync(0xffffffffu, v, 2);
    v += __shfl_down_sync(0xffffffffu, v, 1);
    if (lane == 0) x1[gw] = v;
}

__global__ void k_gat_init(unsigned* gmax, float* gsum, float* gnum, int N) {
    int i = blockIdx.x * blockDim.x + threadIdx.x;
    if (i < N) { gmax[i] = ENC_NEG_INF; gsum[i] = 0.f; gnum[i] = 0.f; }
}

__device__ __forceinline__ void gat_edge(int i, const int* aa, const int* ab, const int* ba,
                                         int E, int Na, int& src, int& dst) {
    if (i < E) { src = aa[i]; dst = aa[E + i]; }
    else if (i < 2 * E) { int j = i - E; src = ab[j]; dst = ab[E + j] + Na; }
    else if (i < 3 * E) { int j = i - 2 * E; src = ba[j] + Na; dst = ba[E + j]; }
    else { int n = i - 3 * E; src = n; dst = n; }
}

__global__ void k_gat_pass1(const int* aa, const int* ab, const int* ba,
                            const float* __restrict__ x1,
                            const float* __restrict__ as_, const float* __restrict__ ad_,
                            unsigned* __restrict__ gmax, int E, int Na, int EG) {
    int i = blockIdx.x * blockDim.x + threadIdx.x;
    if (i >= EG) return;
    int src, dst;
    gat_edge(i, aa, ab, ba, E, Na, src, dst);
    float e = x1[src] * as_[0] + x1[dst] * ad_[0];
    e = (e > 0.f) ? e : 0.2f * e;
    atomicMax(&gmax[dst], fenc(e));
}

__global__ void k_gat_pass2(const int* aa, const int* ab, const int* ba,
                            const float* __restrict__ x1,
                            const float* __restrict__ as_, const float* __restrict__ ad_,
                            const unsigned* __restrict__ gmax,
                            float* __restrict__ gsum, float* __restrict__ gnum,
                            int E, int Na, int EG) {
    int i = blockIdx.x * blockDim.x + threadIdx.x;
    if (i >= EG) return;
    int src, dst;
    gat_edge(i, aa, ab, ba, E, Na, src, dst);
    float e = x1[src] * as_[0] + x1[dst] * ad_[0];
    e = (e > 0.f) ? e : 0.2f * e;
    float w = expf(e - fdec(gmax[dst]));
    atomicAdd(&gsum[dst], w);
    atomicAdd(&gnum[dst], w * x1[src]);
}

__global__ void k_gat_score(const float* gnum, const float* gsum,
                            const float* __restrict__ bgat,
                            float* __restrict__ score, int N) {
    int i = blockIdx.x * blockDim.x + threadIdx.x;
    if (i < N) score[i] = gnum[i] / (gsum[i] + 1e-16f) + bgat[0];
}

// ---------------------------------------------------------------------------
// Final: top-K=8 (jax.lax.top_k semantics: desc, tie -> lower index),
// gated readout, 3-layer MLP, nan_to_num. Single block, 256 threads.
// ---------------------------------------------------------------------------
__global__ void k_final(const float* __restrict__ h, const float* __restrict__ score,
                        float* __restrict__ stmp,
                        const float* __restrict__ W1, const float* __restrict__ b1,
                        const float* __restrict__ W2, const float* __restrict__ b2,
                        const float* __restrict__ W3, const float* __restrict__ b3,
                        float* __restrict__ out, int N) {
    const float NEG_INF = __int_as_float(0xff800000);
    __shared__ float sred[256];
    __shared__ int   sidx[256];
    __shared__ float hp[1024];
    __shared__ int   perm[8];
    __shared__ float vals[8];
    __shared__ float v1[128];
    __shared__ float v2[64];
    int t = threadIdx.x;

    for (int i = t; i < N; i += 256) stmp[i] = score[i];
    __syncthreads();

    for (int k = 0; k < 8; k++) {
        float bv = NEG_INF; int bi = 0x7fffffff;
        for (int i = t; i < N; i += 256) {
            float v = stmp[i];
            if (v > bv || (v == bv && i < bi)) { bv = v; bi = i; }
        }
        sred[t] = bv; sidx[t] = bi;
        __syncthreads();
        for (int s = 128; s > 0; s >>= 1) {
            if (t < s) {
                if (sred[t + s] > sred[t] ||
                    (sred[t + s] == sred[t] && sidx[t + s] < sidx[t])) {
                    sred[t] = sred[t + s]; sidx[t] = sidx[t + s];
                }
            }
            __syncthreads();
        }
        if (t == 0) {
            perm[k] = sidx[0];
            vals[k] = sred[0];
            stmp[sidx[0]] = NEG_INF;
        }
        __syncthreads();
    }

    for (int i = t; i < 1024; i += 256) {
        int k = i >> 7, j = i & 127;
        hp[i] = h[(size_t)perm[k] * 128 + j] * tanhf(vals[k]);
    }
    __syncthreads();

    if (t < 128) {
        float acc = b1[t];
        for (int i = 0; i < 1024; i++) acc += hp[i] * W1[i * 128 + t];
        v1[t] = gelu_f(acc);
    }
    __syncthreads();
    if (t < 64) {
        float acc = b2[t];
        for (int i = 0; i < 128; i++) acc += v1[i] * W2[i * 64 + t];
        v2[t] = gelu_f(acc);
    }
    __syncthreads();
    if (t < 16) {
        float acc = b3[t];
        for (int i = 0; i < 64; i++) acc += v2[i] * W3[i * 16 + t];
        float r = gelu_f(acc);
        if (isnan(r)) r = 0.f;
        else if (isinf(r)) r = (r > 0.f) ? 3.4028234663852886e38f : -3.4028234663852886e38f;
        out[t] = r;
    }
}

// ---------------------------------------------------------------------------
// Host launcher
// ---------------------------------------------------------------------------
static inline int cdiv(int a, int b) { return (a + b - 1) / b; }

extern "C" void kernel_launch(void* const* d_in, const int* in_sizes, int n_in,
                              void* d_out, int out_size) {
    const float* x_a   = (const float*)d_in[0];
    const float* x_b   = (const float*)d_in[1];
    const int*   ei_aa = (const int*)d_in[2];
    const int*   ei_ab = (const int*)d_in[3];
    const int*   ei_ba = (const int*)d_in[4];
    const float* Wkqv  = (const float*)d_in[5];
    const float* bkqv  = (const float*)d_in[6];
    const float* Wout  = (const float*)d_in[7];
    const float* bout  = (const float*)d_in[8];
    const float* skip  = (const float*)d_in[9];
    const float* arel  = (const float*)d_in[10];
    const float* mrel  = (const float*)d_in[11];
    const float* prel  = (const float*)d_in[12];
    const float* ln_g  = (const float*)d_in[13];
    const float* ln_b  = (const float*)d_in[14];
    const float* Wgat  = (const float*)d_in[15];
    const float* att_s = (const float*)d_in[16];
    const float* att_d = (const float*)d_in[17];
    const float* bgat  = (const float*)d_in[18];
    const float* W1    = (const float*)d_in[19];
    const float* b1    = (const float*)d_in[20];
    const float* W2    = (const float*)d_in[21];
    const float* b2    = (const float*)d_in[22];
    const float* W3    = (const float*)d_in[23];
    const float* b3    = (const float*)d_in[24];

    int Na = in_sizes[0] / 128;
    int Nb = in_sizes[1] / 128;
    int N  = Na + Nb;
    int E  = in_sizes[2] / 2;

    float *hbuf, *kqvb, *ktb, *vtb, *alphab, *segsumb, *aggb, *goutb;
    float *x1b, *gsumb, *gnumb, *scoreb, *stmpb;
    unsigned *segmaxb, *gmaxb;
    cudaGetSymbolAddress((void**)&hbuf, g_h);
    cudaGetSymbolAddress((void**)&kqvb, g_kqv);
    cudaGetSymbolAddress((void**)&ktb, g_kt);
    cudaGetSymbolAddress((void**)&vtb, g_vt);
    cudaGetSymbolAddress((void**)&alphab, g_alpha);
    cudaGetSymbolAddress((void**)&segmaxb, g_segmax);
    cudaGetSymbolAddress((void**)&segsumb, g_segsum);
    cudaGetSymbolAddress((void**)&aggb, g_agg);
    cudaGetSymbolAddress((void**)&goutb, g_gout);
    cudaGetSymbolAddress((void**)&x1b, g_x1);
    cudaGetSymbolAddress((void**)&gmaxb, g_gmax);
    cudaGetSymbolAddress((void**)&gsumb, g_gsum);
    cudaGetSymbolAddress((void**)&gnumb, g_gnum);
    cudaGetSymbolAddress((void**)&scoreb, g_score);
    cudaGetSymbolAddress((void**)&stmpb, g_stmp);

    const int etDstOff[3]  = {0, Na, 0};   // dst offset in global node space
    const int etSrcType[3] = {0, 0, 1};    // source node type per edge type
    const int etDstType[3] = {0, 1, 0};    // dest node type per edge type
    const int* eis[3] = {ei_aa, ei_ab, ei_ba};

    // load features
    {
        int tot = (Na > Nb ? Na : Nb) * 128;
        k_copy_in<<<cdiv(tot, 256), 256>>>(x_a, x_b, hbuf, Na * 128, Nb * 128);
    }

    for (int L = 0; L < 3; L++) {
        // ---- per-type kqv GEMMs ----
        for (int t = 0; t < 2; t++) {
            int Nt = t ? Nb : Na;
            const float* A = hbuf + (size_t)(t ? Na : 0) * 128;
            dim3 grid(cdiv(384, 64), cdiv(Nt, 64));
            k_sgemm<<<grid, 256>>>(A, 128,
                                   Wkqv + (size_t)(L * 2 + t) * 128 * 384, 384,
                                   bkqv + (size_t)(L * 2 + t) * 384,
                                   kqvb + (size_t)t * NAC * 384, 384,
                                   Nt, 384, 128);
        }
        // ---- relation transforms ----
        for (int et = 0; et < 3; et++) {
            int st = etSrcType[et];
            int Ns = st ? Nb : Na;
            k_rel_transform<<<512, 128>>>(kqvb + (size_t)st * NAC * 384,
                                          arel + (size_t)(L * 3 + et) * 4096,
                                          mrel + (size_t)(L * 3 + et) * 4096,
                                          ktb + (size_t)et * NAC * 128,
                                          vtb + (size_t)et * NAC * 128, Ns);
        }
        // ---- segment softmax init ----
        k_init_seg<<<cdiv(N * 128, 256), 256>>>(segmaxb, segsumb, aggb, N);
        // ---- pass A: logits + max ----
        for (int et = 0; et < 3; et++) {
            int dt = etDstType[et];
            k_edge_alpha<<<cdiv(E, 8), 256>>>(eis[et],
                                              kqvb + (size_t)dt * NAC * 384,
                                              ktb + (size_t)et * NAC * 128,
                                              prel + (size_t)(L * 3 + et) * 4,
                                              alphab + (size_t)et * EC * 4,
                                              segmaxb, E, etDstOff[et]);
        }
        // ---- pass B: exp + sum ----
        for (int et = 0; et < 3; et++) {
            k_edge_expsum<<<cdiv(E * 4, 256), 256>>>(alphab + (size_t)et * EC * 4,
                                                     eis[et], segmaxb, segsumb,
                                                     E, etDstOff[et]);
        }
        // ---- pass C: normalize + weighted scatter ----
        for (int et = 0; et < 3; et++) {
            k_edge_scatter<<<cdiv(E, 8), 256>>>(alphab + (size_t)et * EC * 4,
                                                eis[et], segsumb,
                                                vtb + (size_t)et * NAC * 128,
                                                aggb, E, etDstOff[et]);
        }
        // ---- finish: gelu(agg) @ Wout + bout; gated skip; LN (L0); gelu ----
        k_gelu<<<cdiv(N * 128, 256), 256>>>(aggb, N * 128);
        for (int t = 0; t < 2; t++) {
            int Nt = t ? Nb : Na;
            size_t off = (size_t)(t ? Na : 0) * 128;
            dim3 grid(cdiv(128, 64), cdiv(Nt, 64));
            k_sgemm<<<grid, 256>>>(aggb + off, 128,
                                   Wout + (size_t)(L * 2 + t) * 128 * 128, 128,
                                   bout + (size_t)(L * 2 + t) * 128,
                                   goutb + off, 128,
                                   Nt, 128, 128);
        }
        for (int t = 0; t < 2; t++) {
            int Nt = t ? Nb : Na;
            size_t off = (size_t)(t ? Na : 0) * 128;
            k_epilogue<<<Nt, 128>>>(goutb + off, hbuf + off,
                                    skip + (L * 2 + t),
                                    ln_g + t * 128, ln_b + t * 128,
                                    (L == 0) ? 1 : 0);
        }
    }

    // ---- GAT scorer + SAGPool + MLP ----
    k_x1<<<cdiv(N * 32, 256), 256>>>(hbuf, Wgat, x1b, N);
    k_gat_init<<<cdiv(N, 256), 256>>>(gmaxb, gsumb, gnumb, N);
    int EG = 3 * E + N;
    k_gat_pass1<<<cdiv(EG, 256), 256>>>(ei_aa, ei_ab, ei_ba, x1b, att_s, att_d,
                                        gmaxb, E, Na, EG);
    k_gat_pass2<<<cdiv(EG, 256), 256>>>(ei_aa, ei_ab, ei_ba, x1b, att_s, att_d,
                                        gmaxb, gsumb, gnumb, E, Na, EG);
    k_gat_score<<<cdiv(N, 256), 256>>>(gnumb, gsumb, bgat, scoreb, N);
    k_final<<<1, 256>>>(hbuf, scoreb, stmpb, W1, b1, W2, b2, W3, b3,
                        (float*)d_out, N);
}

// round 2
// speedup vs baseline: 2.1149x; 2.1149x over previous
#include <cuda_runtime.h>
#include <math.h>
#include <stdint.h>

#define NAC 20000
#define NBC 20000
#define NNC 40000
#define EC  150000

// ---------------------------------------------------------------------------
// Scratch (static device globals)
// ---------------------------------------------------------------------------
__device__ float g_h[NNC * 128];             // node features [a;b]
__device__ float g_feat_a[NAC * 640];        // q|kt0|vt0|kt1|vt1 for type a
__device__ float g_feat_b[NBC * 384];        // q|kt2|vt2 for type b
__device__ float g_wcat[3 * 128 * 1024];     // folded weights per layer
__device__ float g_bcat[3 * 1024];           // folded biases
__device__ float g_alpha[3 * EC * 4];        // CSR-ordered logits
__device__ float g_agg[NNC * 128];
__device__ float g_gout[NNC * 128];
__device__ int   g_deg[NNC + 1];
__device__ int   g_rowptr[NNC + 1];
__device__ int   g_cursor[NNC];
__device__ int   g_cse[3 * EC];              // src | et<<29
__device__ float g_x1[NNC];
__device__ float g_score[NNC];
__device__ float g_stmp[NNC];

__device__ __forceinline__ float gelu_f(float x) {
    return 0.5f * x * (1.0f + erff(x * 0.7071067811865475f));
}

// ---------------------------------------------------------------------------
__global__ void k_copy_in(const float* __restrict__ xa, const float* __restrict__ xb,
                          float* __restrict__ h, int na128, int nb128) {
    int i = blockIdx.x * blockDim.x + threadIdx.x;
    if (i < na128) h[i] = xa[i];
    if (i < nb128) h[na128 + i] = xb[i];
}

// ---------------------------------------------------------------------------
// Fold relation transforms into GEMM weights.
// wcat[L][i][c], c in [0,1024): type a cols [0,640) = q|kt0|vt0|kt1|vt1,
// type b cols [640,1024) = q|kt2|vt2. Row i==128 -> bias into bcat.
// ---------------------------------------------------------------------------
__global__ void k_fold(const float* __restrict__ Wkqv, const float* __restrict__ bkqv,
                       const float* __restrict__ arel, const float* __restrict__ mrel,
                       float* __restrict__ wcat, float* __restrict__ bcat) {
    int idx = blockIdx.x * blockDim.x + threadIdx.x;
    const int TOT = 3 * 129 * 1024;
    if (idx >= TOT) return;
    int L = idx / (129 * 1024);
    int r = idx % (129 * 1024);
    int i = r / 1024;            // 0..128 (128 = bias row)
    int c = r % 1024;
    int type = (c >= 640) ? 1 : 0;
    int cc = c - (type ? 640 : 0);
    int part = cc >> 7, wi = cc & 127;
    const float* Wrow;
    if (i < 128) Wrow = Wkqv + ((size_t)(L * 2 + type) * 128 + i) * 384;
    else         Wrow = bkqv + (size_t)(L * 2 + type) * 384;
    float val;
    if (part == 0) {
        val = Wrow[128 + wi];                       // q part
    } else {
        int et, kv;
        if (type == 0) { et = (part - 1) >> 1; kv = (part - 1) & 1; }
        else           { et = 2;               kv = part - 1; }
        int h = wi >> 5, e = wi & 31;
        const float* rel = (kv ? mrel : arel) + ((size_t)(L * 3 + et) * 4 + h) * 1024 + e;
        const float* wsrc = Wrow + (kv ? 256 : 0) + h * 32;
        float s = 0.f;
#pragma unroll
        for (int d = 0; d < 32; d++) s += wsrc[d] * rel[d * 32];
        val = s;
    }
    if (i < 128) wcat[(size_t)L * 131072 + (size_t)i * 1024 + c] = val;
    else         bcat[L * 1024 + c] = val;
}

// ---------------------------------------------------------------------------
// SGEMM: C[M,N] = act(A)[M,128] @ B[128,N] + bias. 128x64 tile, 8x4 micro.
// N must be a multiple of 64. K fixed = 128.
// ---------------------------------------------------------------------------
template <bool GELU_A>
__global__ void k_gemm128(const float* __restrict__ A, int lda,
                          const float* __restrict__ B, int ldb,
                          const float* __restrict__ bias,
                          float* __restrict__ C, int ldc, int M) {
    __shared__ __align__(16) float As[16][128];
    __shared__ __align__(16) float Bs[16][64];
    int tid = threadIdx.x;
    int row0 = blockIdx.y * 128, col0 = blockIdx.x * 64;
    int tx = tid & 15;       // N dir (4 cols)
    int ty = tid >> 4;       // M dir (8 rows)
    float acc[8][4] = {};

    int arow = tid >> 1;
    int ak   = (tid & 1) << 3;
    int bk = tid >> 4, bn = (tid & 15) << 2;
    const float* Aptr = A + (size_t)(row0 + arow) * lda + ak;
    bool aval = (row0 + arow) < M;
    const float* Bptr = B + (size_t)bk * ldb + col0 + bn;

    for (int k0 = 0; k0 < 128; k0 += 16) {
        float4 a0 = make_float4(0.f, 0.f, 0.f, 0.f);
        float4 a1 = make_float4(0.f, 0.f, 0.f, 0.f);
        if (aval) {
            a0 = *(const float4*)(Aptr + k0);
            a1 = *(const float4*)(Aptr + k0 + 4);
        }
        if (GELU_A) {
            a0.x = gelu_f(a0.x); a0.y = gelu_f(a0.y); a0.z = gelu_f(a0.z); a0.w = gelu_f(a0.w);
            a1.x = gelu_f(a1.x); a1.y = gelu_f(a1.y); a1.z = gelu_f(a1.z); a1.w = gelu_f(a1.w);
        }
        As[ak + 0][arow] = a0.x; As[ak + 1][arow] = a0.y;
        As[ak + 2][arow] = a0.z; As[ak + 3][arow] = a0.w;
        As[ak + 4][arow] = a1.x; As[ak + 5][arow] = a1.y;
        As[ak + 6][arow] = a1.z; As[ak + 7][arow] = a1.w;
        *(float4*)&Bs[bk][bn] = *(const float4*)(Bptr + (size_t)k0 * ldb);
        __syncthreads();
#pragma unroll
        for (int kk = 0; kk < 16; kk++) {
            float4 b = *(const float4*)&Bs[kk][tx * 4];
            float4 x0 = *(const float4*)&As[kk][ty * 8];
            float4 x1 = *(const float4*)&As[kk][ty * 8 + 4];
            acc[0][0] += x0.x * b.x; acc[0][1] += x0.x * b.y; acc[0][2] += x0.x * b.z; acc[0][3] += x0.x * b.w;
            acc[1][0] += x0.y * b.x; acc[1][1] += x0.y * b.y; acc[1][2] += x0.y * b.z; acc[1][3] += x0.y * b.w;
            acc[2][0] += x0.z * b.x; acc[2][1] += x0.z * b.y; acc[2][2] += x0.z * b.z; acc[2][3] += x0.z * b.w;
            acc[3][0] += x0.w * b.x; acc[3][1] += x0.w * b.y; acc[3][2] += x0.w * b.z; acc[3][3] += x0.w * b.w;
            acc[4][0] += x1.x * b.x; acc[4][1] += x1.x * b.y; acc[4][2] += x1.x * b.z; acc[4][3] += x1.x * b.w;
            acc[5][0] += x1.y * b.x; acc[5][1] += x1.y * b.y; acc[5][2] += x1.y * b.z; acc[5][3] += x1.y * b.w;
            acc[6][0] += x1.z * b.x; acc[6][1] += x1.z * b.y; acc[6][2] += x1.z * b.z; acc[6][3] += x1.z * b.w;
            acc[7][0] += x1.w * b.x; acc[7][1] += x1.w * b.y; acc[7][2] += x1.w * b.z; acc[7][3] += x1.w * b.w;
        }
        __syncthreads();
    }
    float4 bb = *(const float4*)(bias + col0 + tx * 4);
#pragma unroll
    for (int i = 0; i < 8; i++) {
        int rr = row0 + ty * 8 + i;
        if (rr >= M) break;
        float4 o;
        o.x = acc[i][0] + bb.x; o.y = acc[i][1] + bb.y;
        o.z = acc[i][2] + bb.z; o.w = acc[i][3] + bb.w;
        *(float4*)(C + (size_t)rr * ldc + col0 + tx * 4) = o;
    }
}

// ---------------------------------------------------------------------------
// CSR build
// ---------------------------------------------------------------------------
__global__ void k_zero_deg(int* d, int n) {
    int i = blockIdx.x * blockDim.x + threadIdx.x;
    if (i < n) d[i] = 0;
}
__global__ void k_count(const int* __restrict__ aa, const int* __restrict__ ab,
                        const int* __restrict__ ba, int* __restrict__ deg, int E, int Na) {
    int i = blockIdx.x * blockDim.x + threadIdx.x;
    if (i >= 3 * E) return;
    int dst;
    if (i < E) dst = aa[E + i];
    else if (i < 2 * E) dst = ab[E + (i - E)] + Na;
    else dst = ba[E + (i - 2 * E)];
    atomicAdd(&deg[dst + 1], 1);
}
__global__ void k_scan(const int* __restrict__ deg, int* __restrict__ rowptr,
                       int* __restrict__ cursor, int N) {
    __shared__ int buf[1024];
    __shared__ int carry;
    if (threadIdx.x == 0) carry = 0;
    __syncthreads();
    for (int base = 0; base <= N; base += 1024) {
        int i = base + threadIdx.x;
        int v = (i <= N) ? deg[i] : 0;
        buf[threadIdx.x] = v;
        __syncthreads();
        for (int o = 1; o < 1024; o <<= 1) {
            int u = (threadIdx.x >= o) ? buf[threadIdx.x - o] : 0;
            __syncthreads();
            buf[threadIdx.x] += u;
            __syncthreads();
        }
        int out = buf[threadIdx.x] + carry;
        if (i <= N) { rowptr[i] = out; if (i < N) cursor[i] = out; }
        __syncthreads();
        if (threadIdx.x == 0) carry += buf[1023];
        __syncthreads();
    }
}
__global__ void k_fill(const int* __restrict__ aa, const int* __restrict__ ab,
                       const int* __restrict__ ba, int* __restrict__ cursor,
                       int* __restrict__ cse, int E, int Na) {
    int i = blockIdx.x * blockDim.x + threadIdx.x;
    if (i >= 3 * E) return;
    int src, dst, et;
    if (i < E)            { et = 0; src = aa[i]; dst = aa[E + i]; }
    else if (i < 2 * E)   { et = 1; int j = i - E;     src = ab[j]; dst = ab[E + j] + Na; }
    else                  { et = 2; int j = i - 2 * E; src = ba[j]; dst = ba[E + j]; }
    int pos = atomicAdd(&cursor[dst], 1);
    cse[pos] = src | (et << 29);
}

// ---------------------------------------------------------------------------
// Fused HGT edge softmax-aggregate. One warp per dst node. No atomics.
// Lane l covers elems 4l..4l+3; head h = l>>3.
// ---------------------------------------------------------------------------
__global__ void k_hgt_edges(const float* __restrict__ fa, const float* __restrict__ fb,
                            const int* __restrict__ rowptr, const int* __restrict__ cse,
                            const float* __restrict__ prelL,
                            float* __restrict__ alpha, float* __restrict__ agg,
                            int Na, int N) {
    __shared__ float sp[12];
    if (threadIdx.x < 12) sp[threadIdx.x] = prelL[threadIdx.x];
    __syncthreads();
    int warp = (blockIdx.x * blockDim.x + threadIdx.x) >> 5;
    int lane = threadIdx.x & 31;
    if (warp >= N) return;
    int n = warp;
    const float* qrow = (n < Na) ? (fa + (size_t)n * 640) : (fb + (size_t)(n - Na) * 384);
    float4 q4 = *(const float4*)(qrow + lane * 4);
    int h = lane >> 3;
    int beg = rowptr[n], end = rowptr[n + 1];
    float mx = -INFINITY;
    for (int idx = beg; idx < end; idx++) {
        int p = cse[idx];
        int et = p >> 29, src = p & 0x1FFFFFFF;
        const float* kb = (et < 2) ? (fa + (size_t)src * 640 + 128 + (et << 8))
                                   : (fb + (size_t)src * 384 + 128);
        float4 k4 = *(const float4*)(kb + lane * 4);
        float s = q4.x * k4.x + q4.y * k4.y + q4.z * k4.z + q4.w * k4.w;
        s += __shfl_xor_sync(0xffffffffu, s, 1);
        s += __shfl_xor_sync(0xffffffffu, s, 2);
        s += __shfl_xor_sync(0xffffffffu, s, 4);
        float lg = s * sp[et * 4 + h] * 0.17677669529663687f;
        if ((lane & 7) == 0) alpha[(size_t)idx * 4 + h] = lg;
        mx = fmaxf(mx, lg);
    }
    float sum = 0.f;
    float4 acc = make_float4(0.f, 0.f, 0.f, 0.f);
    for (int idx = beg; idx < end; idx++) {
        int p = cse[idx];
        int et = p >> 29, src = p & 0x1FFFFFFF;
        const float* vb = (et < 2) ? (fa + (size_t)src * 640 + 256 + (et << 8))
                                   : (fb + (size_t)src * 384 + 256);
        float lg = alpha[(size_t)idx * 4 + h];
        float w = expf(lg - mx);
        sum += w;
        float4 v4 = *(const float4*)(vb + lane * 4);
        acc.x += w * v4.x; acc.y += w * v4.y; acc.z += w * v4.z; acc.w += w * v4.w;
    }
    float inv = 1.f / (sum + 1e-16f);
    acc.x *= inv; acc.y *= inv; acc.z *= inv; acc.w *= inv;
    *(float4*)(agg + (size_t)n * 128 + lane * 4) = acc;
}

// ---------------------------------------------------------------------------
// Epilogue: h = gelu( [LN]( s*g + (1-s)*h ) )
// ---------------------------------------------------------------------------
__global__ void k_epilogue(const float* __restrict__ g, float* __restrict__ h,
                           const float* __restrict__ skipv,
                           const float* __restrict__ lng, const float* __restrict__ lnb,
                           int doLN) {
    int n = blockIdx.x, t = threadIdx.x;
    float s = 1.0f / (1.0f + expf(-skipv[0]));
    size_t idx = (size_t)n * 128 + t;
    float v = s * g[idx] + (1.0f - s) * h[idx];
    if (doLN) {
        float sv = v, sq = v * v;
#pragma unroll
        for (int o = 16; o > 0; o >>= 1) {
            sv += __shfl_down_sync(0xffffffffu, sv, o);
            sq += __shfl_down_sync(0xffffffffu, sq, o);
        }
        __shared__ float s1[4], s2[4];
        int w = t >> 5;
        if ((t & 31) == 0) { s1[w] = sv; s2[w] = sq; }
        __syncthreads();
        float mu = (s1[0] + s1[1] + s1[2] + s1[3]) * 0.0078125f;
        float eq = (s2[0] + s2[1] + s2[2] + s2[3]) * 0.0078125f;
        float var = eq - mu * mu;
        v = (v - mu) * rsqrtf(var + 1e-5f) * lng[t] + lnb[t];
    }
    h[idx] = gelu_f(v);
}

// ---------------------------------------------------------------------------
// GAT scorer via CSR (+analytic self loops). Thread per node.
// ---------------------------------------------------------------------------
__global__ void k_x1(const float* __restrict__ h, const float* __restrict__ Wg,
                     float* __restrict__ x1, int N) {
    int gw = (blockIdx.x * blockDim.x + threadIdx.x) >> 5;
    int lane = threadIdx.x & 31;
    if (gw >= N) return;
    const float* row = h + (size_t)gw * 128;
    float v = row[lane] * Wg[lane] + row[32 + lane] * Wg[32 + lane]
            + row[64 + lane] * Wg[64 + lane] + row[96 + lane] * Wg[96 + lane];
    v += __shfl_down_sync(0xffffffffu, v, 16);
    v += __shfl_down_sync(0xffffffffu, v, 8);
    v += __shfl_down_sync(0xffffffffu, v, 4);
    v += __shfl_down_sync(0xffffffffu, v, 2);
    v += __shfl_down_sync(0xffffffffu, v, 1);
    if (lane == 0) x1[gw] = v;
}

__global__ void k_gat(const float* __restrict__ x1, const int* __restrict__ rowptr,
                      const int* __restrict__ cse, const float* __restrict__ as_,
                      const float* __restrict__ ad_, const float* __restrict__ bg,
                      float* __restrict__ score, int Na, int N) {
    int n = blockIdx.x * blockDim.x + threadIdx.x;
    if (n >= N) return;
    float a_s = as_[0], a_d = ad_[0];
    float xd = x1[n];
    float eself = xd * (a_s + a_d);
    eself = eself > 0.f ? eself : 0.2f * eself;
    float m = eself;
    int beg = rowptr[n], end = rowptr[n + 1];
    for (int i = beg; i < end; i++) {
        int p = cse[i];
        int src = (p & 0x1FFFFFFF) + (((p >> 29) == 2) ? Na : 0);
        float e = x1[src] * a_s + xd * a_d;
        e = e > 0.f ? e : 0.2f * e;
        m = fmaxf(m, e);
    }
    float w = expf(eself - m), s = w, num = w * xd;
    for (int i = beg; i < end; i++) {
        int p = cse[i];
        int src = (p & 0x1FFFFFFF) + (((p >> 29) == 2) ? Na : 0);
        float e = x1[src] * a_s + xd * a_d;
        e = e > 0.f ? e : 0.2f * e;
        float ww = expf(e - m);
        s += ww; num += ww * x1[src];
    }
    score[n] = num / (s + 1e-16f) + bg[0];
}

// ---------------------------------------------------------------------------
// Final: top-K=8, gated readout, 3-layer MLP, nan_to_num.
// ---------------------------------------------------------------------------
__global__ void k_final(const float* __restrict__ h, const float* __restrict__ score,
                        float* __restrict__ stmp,
                        const float* __restrict__ W1, const float* __restrict__ b1,
                        const float* __restrict__ W2, const float* __restrict__ b2,
                        const float* __restrict__ W3, const float* __restrict__ b3,
                        float* __restrict__ out, int N) {
    const float NEG_INF = __int_as_float(0xff800000);
    __shared__ float sred[256];
    __shared__ int   sidx[256];
    __shared__ float hp[1024];
    __shared__ int   perm[8];
    __shared__ float vals[8];
    __shared__ float v1[128];
    __shared__ float v2[64];
    int t = threadIdx.x;

    for (int i = t; i < N; i += 256) stmp[i] = score[i];
    __syncthreads();

    for (int k = 0; k < 8; k++) {
        float bv = NEG_INF; int bi = 0x7fffffff;
        for (int i = t; i < N; i += 256) {
            float v = stmp[i];
            if (v > bv || (v == bv && i < bi)) { bv = v; bi = i; }
        }
        sred[t] = bv; sidx[t] = bi;
        __syncthreads();
        for (int s = 128; s > 0; s >>= 1) {
            if (t < s) {
                if (sred[t + s] > sred[t] ||
                    (sred[t + s] == sred[t] && sidx[t + s] < sidx[t])) {
                    sred[t] = sred[t + s]; sidx[t] = sidx[t + s];
                }
            }
            __syncthreads();
        }
        if (t == 0) { perm[k] = sidx[0]; vals[k] = sred[0]; stmp[sidx[0]] = NEG_INF; }
        __syncthreads();
    }

    for (int i = t; i < 1024; i += 256) {
        int k = i >> 7, j = i & 127;
        hp[i] = h[(size_t)perm[k] * 128 + j] * tanhf(vals[k]);
    }
    __syncthreads();

    if (t < 128) {
        float acc = b1[t];
        for (int i = 0; i < 1024; i++) acc += hp[i] * W1[i * 128 + t];
        v1[t] = gelu_f(acc);
    }
    __syncthreads();
    if (t < 64) {
        float acc = b2[t];
        for (int i = 0; i < 128; i++) acc += v1[i] * W2[i * 64 + t];
        v2[t] = gelu_f(acc);
    }
    __syncthreads();
    if (t < 16) {
        float acc = b3[t];
        for (int i = 0; i < 64; i++) acc += v2[i] * W3[i * 16 + t];
        float r = gelu_f(acc);
        if (isnan(r)) r = 0.f;
        else if (isinf(r)) r = (r > 0.f) ? 3.4028234663852886e38f : -3.4028234663852886e38f;
        out[t] = r;
    }
}

// ---------------------------------------------------------------------------
static inline int cdiv(int a, int b) { return (a + b - 1) / b; }

extern "C" void kernel_launch(void* const* d_in, const int* in_sizes, int n_in,
                              void* d_out, int out_size) {
    const float* x_a   = (const float*)d_in[0];
    const float* x_b   = (const float*)d_in[1];
    const int*   ei_aa = (const int*)d_in[2];
    const int*   ei_ab = (const int*)d_in[3];
    const int*   ei_ba = (const int*)d_in[4];
    const float* Wkqv  = (const float*)d_in[5];
    const float* bkqv  = (const float*)d_in[6];
    const float* Wout  = (const float*)d_in[7];
    const float* bout  = (const float*)d_in[8];
    const float* skip  = (const float*)d_in[9];
    const float* arel  = (const float*)d_in[10];
    const float* mrel  = (const float*)d_in[11];
    const float* prel  = (const float*)d_in[12];
    const float* ln_g  = (const float*)d_in[13];
    const float* ln_b  = (const float*)d_in[14];
    const float* Wgat  = (const float*)d_in[15];
    const float* att_s = (const float*)d_in[16];
    const float* att_d = (const float*)d_in[17];
    const float* bgat  = (const float*)d_in[18];
    const float* W1    = (const float*)d_in[19];
    const float* b1    = (const float*)d_in[20];
    const float* W2    = (const float*)d_in[21];
    const float* b2    = (const float*)d_in[22];
    const float* W3    = (const float*)d_in[23];
    const float* b3    = (const float*)d_in[24];

    int Na = in_sizes[0] / 128;
    int Nb = in_sizes[1] / 128;
    int N  = Na + Nb;
    int E  = in_sizes[2] / 2;

    float *hbuf, *fa, *fb, *wcat, *bcat, *alphab, *aggb, *goutb, *x1b, *scoreb, *stmpb;
    int *degb, *rowptrb, *cursorb, *cseb;
    cudaGetSymbolAddress((void**)&hbuf, g_h);
    cudaGetSymbolAddress((void**)&fa, g_feat_a);
    cudaGetSymbolAddress((void**)&fb, g_feat_b);
    cudaGetSymbolAddress((void**)&wcat, g_wcat);
    cudaGetSymbolAddress((void**)&bcat, g_bcat);
    cudaGetSymbolAddress((void**)&alphab, g_alpha);
    cudaGetSymbolAddress((void**)&aggb, g_agg);
    cudaGetSymbolAddress((void**)&goutb, g_gout);
    cudaGetSymbolAddress((void**)&degb, g_deg);
    cudaGetSymbolAddress((void**)&rowptrb, g_rowptr);
    cudaGetSymbolAddress((void**)&cursorb, g_cursor);
    cudaGetSymbolAddress((void**)&cseb, g_cse);
    cudaGetSymbolAddress((void**)&x1b, g_x1);
    cudaGetSymbolAddress((void**)&scoreb, g_score);
    cudaGetSymbolAddress((void**)&stmpb, g_stmp);

    // inputs + CSR build + weight folding (reused across layers)
    {
        int tot = (Na > Nb ? Na : Nb) * 128;
        k_copy_in<<<cdiv(tot, 256), 256>>>(x_a, x_b, hbuf, Na * 128, Nb * 128);
    }
    k_zero_deg<<<cdiv(N + 1, 256), 256>>>(degb, N + 1);
    k_count<<<cdiv(3 * E, 256), 256>>>(ei_aa, ei_ab, ei_ba, degb, E, Na);
    k_scan<<<1, 1024>>>(degb, rowptrb, cursorb, N);
    k_fill<<<cdiv(3 * E, 256), 256>>>(ei_aa, ei_ab, ei_ba, cursorb, cseb, E, Na);
    k_fold<<<cdiv(3 * 129 * 1024, 256), 256>>>(Wkqv, bkqv, arel, mrel, wcat, bcat);

    int mbA = cdiv(Na, 128), mbB = cdiv(Nb, 128), mbN = cdiv(N, 128);

    for (int L = 0; L < 3; L++) {
        // feature GEMMs (q + folded kt/vt)
        k_gemm128<false><<<dim3(10, mbA), 256>>>(hbuf, 128,
            wcat + (size_t)L * 131072, 1024, bcat + L * 1024, fa, 640, Na);
        k_gemm128<false><<<dim3(6, mbB), 256>>>(hbuf + (size_t)Na * 128, 128,
            wcat + (size_t)L * 131072 + 640, 1024, bcat + L * 1024 + 640, fb, 384, Nb);
        // fused edge softmax-aggregate
        k_hgt_edges<<<cdiv(N * 32, 256), 256>>>(fa, fb, rowptrb, cseb,
            prel + L * 12, alphab, aggb, Na, N);
        // out GEMM with fused gelu-on-input
        for (int t = 0; t < 2; t++) {
            int Nt = t ? Nb : Na;
            size_t off = (size_t)(t ? Na : 0) * 128;
            k_gemm128<true><<<dim3(2, cdiv(Nt, 128)), 256>>>(aggb + off, 128,
                Wout + (size_t)(L * 2 + t) * 16384, 128,
                bout + (size_t)(L * 2 + t) * 128, goutb + off, 128, Nt);
        }
        for (int t = 0; t < 2; t++) {
            int Nt = t ? Nb : Na;
            size_t off = (size_t)(t ? Na : 0) * 128;
            k_epilogue<<<Nt, 128>>>(goutb + off, hbuf + off, skip + (L * 2 + t),
                                    ln_g + t * 128, ln_b + t * 128, (L == 0) ? 1 : 0);
        }
    }

    // GAT scorer + SAGPool + MLP
    k_x1<<<cdiv(N * 32, 256), 256>>>(hbuf, Wgat, x1b, N);
    k_gat<<<cdiv(N, 256), 256>>>(x1b, rowptrb, cseb, att_s, att_d, bgat, scoreb, Na, N);
    k_final<<<1, 256>>>(hbuf, scoreb, stmpb, W1, b1, W2, b2, W3, b3, (float*)d_out, N);
}